// round 1
// baseline (speedup 1.0000x reference)
#include <cuda_runtime.h>
#include <cuda_bf16.h>
#include <cstdint>

// Problem constants
#define TT   512
#define BB   128
#define NIN  256
#define NH   1024
#define NOUT 32

// ---------------- device scratch (no allocations allowed) ----------------
__device__ unsigned int g_idx[TT * BB * 64];      // per (t,b): up to 256 uint8 indices (64 words) = 16 MB
__device__ int          g_cnt[TT * BB];           // active-input counts
__device__ unsigned int g_zbits[TT * BB * 32];    // hidden spikes as bitmask: 32 words per (t,b) = 8 MB
__device__ float        g_whT[NIN * NH];          // transposed hidden weights [i][h] = 1 MB
__device__ float        g_co[TT * BB * NOUT];     // output-layer currents = 8 MB

// ---------------- K0: transpose w_h [H][I] -> [I][H] ----------------
__global__ void transpose_wh_kernel(const float* __restrict__ w_h) {
    int k = blockIdx.x * blockDim.x + threadIdx.x;
    if (k < NH * NIN) {
        int h = k >> 8;       // NIN = 256
        int i = k & 255;
        g_whT[i * NH + h] = w_h[k];
    }
}

// ---------------- K1: compact input spikes into index lists ----------------
__global__ __launch_bounds__(256) void compact_kernel(const float* __restrict__ spikes) {
    int tb  = blockIdx.x;              // (t*BB + b)
    int tid = threadIdx.x;             // input index i
    float s = spikes[(size_t)tb * NIN + tid];
    bool p  = (s != 0.0f);
    unsigned m = __ballot_sync(0xffffffffu, p);

    __shared__ int wcnt[8];
    int warp = tid >> 5, lane = tid & 31;
    if (lane == 0) wcnt[warp] = __popc(m);
    __syncthreads();

    int base = 0;
#pragma unroll
    for (int w = 0; w < 8; w++) base += (w < warp) ? wcnt[w] : 0;

    if (p) {
        int pos = base + __popc(m & ((1u << lane) - 1u));
        ((unsigned char*)g_idx)[(size_t)tb * 256 + pos] = (unsigned char)tid;
    }
    if (tid == 0) {
        int tot = 0;
#pragma unroll
        for (int w = 0; w < 8; w++) tot += wcnt[w];
        g_cnt[tb] = tot;
    }
}

// ---------------- K2: fused sparse projection + CUBA LIF scan ----------------
// Grid: (NH/128, BB/8) = (8,16). Block: 512 threads.
// Thread layout: bl = tid>>6 (batch within group of 8), u = tid&63.
// Each thread owns hidden neurons h0+u and h0+64+u for batch b0+bl.
// Shared: weight tile wT[256][128] (131072 B) + double-buffered idx staging.
#define SMEM_B_BYTES (131072 + 4096 + 64)

__global__ __launch_bounds__(512, 1) void lif_kernel() {
    extern __shared__ float smem[];
    float*        s_w   = smem;                                  // [256*128]
    unsigned int* s_idx = (unsigned int*)(smem + 256 * 128);     // [2][8][64]
    int*          s_cnt = (int*)(s_idx + 2 * 8 * 64);            // [2][8]

    int tid = threadIdx.x;
    int h0  = blockIdx.x * 128;
    int b0  = blockIdx.y * 8;

    // load transposed weight tile: s_w[i*128 + j] = wT[i][h0+j]
    for (int k = tid; k < 256 * 128; k += 512)
        s_w[k] = g_whT[(k >> 7) * NH + h0 + (k & 127)];

    // stage t = 0
    {
        int sb = tid >> 6, sw = tid & 63;
        int tb  = 0 * BB + (b0 + sb);
        int cnt = g_cnt[tb];
        if (sw == 0) s_cnt[0 * 8 + sb] = cnt;
        if (sw * 4 < cnt) s_idx[(0 * 8 + sb) * 64 + sw] = g_idx[(size_t)tb * 64 + sw];
    }
    __syncthreads();

    int bl   = tid >> 6;
    int u    = tid & 63;
    int b    = b0 + bl;
    int lane = tid & 31;

    float v0 = 0.f, v1 = 0.f, cur_i0 = 0.f, cur_i1 = 0.f;

    for (int t = 0; t < TT; t++) {
        int cur = t & 1, nxt = cur ^ 1;

        // stage t+1 into the other buffer (overlaps with compute)
        if (t + 1 < TT) {
            int sb = tid >> 6, sw = tid & 63;
            int tb  = (t + 1) * BB + (b0 + sb);
            int cnt = g_cnt[tb];
            if (sw == 0) s_cnt[nxt * 8 + sb] = cnt;
            if (sw * 4 < cnt) s_idx[(nxt * 8 + sb) * 64 + sw] = g_idx[(size_t)tb * 64 + sw];
        }

        // sparse gather: c = sum over active inputs of weight column
        int cnt = s_cnt[cur * 8 + bl];
        const unsigned int* wl = &s_idx[(cur * 8 + bl) * 64];
        float c0 = 0.f, c1 = 0.f;
        int nw = cnt >> 2;
        for (int kw = 0; kw < nw; kw++) {
            unsigned int wd = wl[kw];                       // broadcast LDS
            int a0 = (int)(wd & 255u) << 7;
            int a1 = (int)((wd >> 8) & 255u) << 7;
            int a2 = (int)((wd >> 16) & 255u) << 7;
            int a3 = (int)(wd >> 24) << 7;
            c0 += s_w[a0 + u];      c1 += s_w[a0 + 64 + u];
            c0 += s_w[a1 + u];      c1 += s_w[a1 + 64 + u];
            c0 += s_w[a2 + u];      c1 += s_w[a2 + 64 + u];
            c0 += s_w[a3 + u];      c1 += s_w[a3 + 64 + u];
        }
        int rem = cnt & 3;
        if (rem) {
            unsigned int wd = wl[nw];
            for (int r = 0; r < rem; r++) {
                int a = (int)((wd >> (8 * r)) & 255u) << 7;
                c0 += s_w[a + u];   c1 += s_w[a + 64 + u];
            }
        }

        // CUBA LIF update (exactly mirrors reference fp32 expressions)
        cur_i0 = cur_i0 * 0.875f + c0;
        v0 = v0 + 0.125f * (cur_i0 - v0);
        bool z0 = (v0 - 1.0f) > 0.0f;
        if (z0) v0 = 0.0f;

        cur_i1 = cur_i1 * 0.875f + c1;
        v1 = v1 + 0.125f * (cur_i1 - v1);
        bool z1 = (v1 - 1.0f) > 0.0f;
        if (z1) v1 = 0.0f;

        unsigned mz0 = __ballot_sync(0xffffffffu, z0);
        unsigned mz1 = __ballot_sync(0xffffffffu, z1);
        if (lane == 0) {
            int wq = u >> 5;   // 0 or 1 (warp half within the 64-h slice)
            unsigned int* zp = &g_zbits[((size_t)t * BB + b) * 32 + (h0 >> 5)];
            zp[wq]     = mz0;  // h in [h0,      h0+63 ]
            zp[2 + wq] = mz1;  // h in [h0+64,   h0+127]
        }
        __syncthreads();
    }
}

// ---------------- K3: output-layer currents from spike bitmasks ----------------
// Grid: BB blocks (one per batch). Block 512 = 16 warps; warp handles t strided.
// smem: w_o transposed with pad-33 stride: [1024][33] floats = 135168 B.
#define SMEM_C_BYTES (NH * 33 * 4)

__global__ __launch_bounds__(512, 1) void cout_kernel(const float* __restrict__ w_o) {
    extern __shared__ float s_wT[];   // [h*33 + o]
    int tid = threadIdx.x;
    for (int k = tid; k < NOUT * NH; k += 512) {
        int o = k >> 10;
        int h = k & 1023;
        s_wT[h * 33 + o] = w_o[k];
    }
    __syncthreads();

    int b = blockIdx.x;
    int warp = tid >> 5, lane = tid & 31;

    for (int t = warp; t < TT; t += 16) {
        unsigned m = g_zbits[((size_t)t * BB + b) * 32 + lane];
        float c = 0.f;
#pragma unroll 8
        for (int wi = 0; wi < 32; wi++) {
            unsigned mw = __shfl_sync(0xffffffffu, m, wi);
            int hb = wi << 5;
            while (mw) {
                int p = __ffs(mw) - 1;
                mw &= mw - 1;
                c += s_wT[(hb + p) * 33 + lane];
            }
        }
        g_co[((size_t)t * BB + b) * 32 + lane] = c;
    }
}

// ---------------- K4: CUBA LI readout scan ----------------
__global__ __launch_bounds__(256) void li_kernel(float* __restrict__ out) {
    int gid = blockIdx.x * blockDim.x + threadIdx.x;  // 0 .. B*NOUT-1 (4096)
    float v = 0.f, cur = 0.f;
    for (int t = 0; t < TT; t++) {
        float c = g_co[(size_t)t * (BB * NOUT) + gid];
        cur = cur * 0.875f + c;
        v = v + 0.125f * (cur - v);
        out[(size_t)t * (BB * NOUT) + gid] = v;
    }
}

// ---------------- launch ----------------
extern "C" void kernel_launch(void* const* d_in, const int* in_sizes, int n_in,
                              void* d_out, int out_size) {
    const float* spikes = (const float*)d_in[0];   // [512,128,256]
    const float* w_h    = (const float*)d_in[1];   // [1024,256]
    const float* w_o    = (const float*)d_in[2];   // [32,1024]
    float* out = (float*)d_out;                    // [512,128,32]

    cudaFuncSetAttribute(lif_kernel,  cudaFuncAttributeMaxDynamicSharedMemorySize, SMEM_B_BYTES);
    cudaFuncSetAttribute(cout_kernel, cudaFuncAttributeMaxDynamicSharedMemorySize, SMEM_C_BYTES);

    transpose_wh_kernel<<<(NH * NIN + 1023) / 1024, 1024>>>(w_h);
    compact_kernel<<<TT * BB, 256>>>(spikes);
    lif_kernel<<<dim3(NH / 128, BB / 8), 512, SMEM_B_BYTES>>>();
    cout_kernel<<<BB, 512, SMEM_C_BYTES>>>(w_o);
    li_kernel<<<(BB * NOUT) / 256, 256>>>(out);
}

// round 2
// speedup vs baseline: 1.8365x; 1.8365x over previous
#include <cuda_runtime.h>
#include <cstdint>

#define TT   512
#define BB   128
#define NIN  256
#define NH   1024
#define NOUT 32

// ---------------- device scratch ----------------
__device__ unsigned int g_idx[TT * BB * 64];      // per (t,b): up to 256 uint8 indices
__device__ int          g_cnt[TT * BB];
__device__ unsigned int g_zbits[TT * BB * 32];    // hidden spike bitmask (permuted even/odd layout)
__device__ float        g_whT[NIN * NH];          // transposed hidden weights [i][h]

// packed f32x2 add (sm_103a)
#define ADD2(acc, val) asm("add.rn.f32x2 %0, %1, %2;" : "=l"(acc) : "l"(acc), "l"(val))

// ---------------- K0: transpose w_h [H][I] -> [I][H] ----------------
__global__ void transpose_wh_kernel(const float* __restrict__ w_h) {
    int k = blockIdx.x * blockDim.x + threadIdx.x;
    if (k < NH * NIN) {
        int h = k >> 8;
        int i = k & 255;
        g_whT[i * NH + h] = w_h[k];
    }
}

// ---------------- K1: compact input spikes into index lists ----------------
__global__ __launch_bounds__(256) void compact_kernel(const float* __restrict__ spikes) {
    int tb  = blockIdx.x;
    int tid = threadIdx.x;
    float s = spikes[(size_t)tb * NIN + tid];
    bool p  = (s != 0.0f);
    unsigned m = __ballot_sync(0xffffffffu, p);

    __shared__ int wcnt[8];
    int warp = tid >> 5, lane = tid & 31;
    if (lane == 0) wcnt[warp] = __popc(m);
    __syncthreads();

    int base = 0;
#pragma unroll
    for (int w = 0; w < 8; w++) base += (w < warp) ? wcnt[w] : 0;

    if (p) {
        int pos = base + __popc(m & ((1u << lane) - 1u));
        ((unsigned char*)g_idx)[(size_t)tb * 256 + pos] = (unsigned char)tid;
    }
    if (tid == 0) {
        int tot = 0;
#pragma unroll
        for (int w = 0; w < 8; w++) tot += wcnt[w];
        g_cnt[tb] = tot;
    }
}

// ---------------- K2: fused sparse projection + CUBA LIF scan (barrier-free) ----------------
// Grid (16,16): bx = h-tile (64 h), by = batch group (8 b). Block 256 = 8 warps.
// Warp = one (b, h-tile); thread owns h-pair (h0+2u, h0+2u+1) via float2.
// smem: weight tile as float2 [256][32] = 64 KB. NO per-step barriers.
#define LIF_SMEM (256 * 32 * 8)

__global__ __launch_bounds__(256, 3) void lif_kernel() {
    extern __shared__ unsigned long long s_w2[];   // [i*32 + u] = (w[i][h0+2u], w[i][h0+2u+1])
    int tid = threadIdx.x;
    int h0  = blockIdx.x * 64;
    int b0  = blockIdx.y * 8;

    for (int k = tid; k < 256 * 32; k += 256) {
        int i = k >> 5, u = k & 31;
        s_w2[k] = *(const unsigned long long*)(g_whT + i * NH + h0 + 2 * u);
    }
    __syncthreads();   // only barrier in the kernel

    int u    = tid & 31;           // lane
    int bl   = tid >> 5;           // warp = batch within group
    int b    = b0 + bl;
    const unsigned long long* wrow = s_w2 + u;

    // prefetch t=0 index list (first 32 indices + count) into registers
    size_t tb = (size_t)b;
    uint4 p0 = ((const uint4*)(g_idx + tb * 64))[0];
    uint4 p1 = ((const uint4*)(g_idx + tb * 64))[1];
    int cnt_n = g_cnt[tb];

    float v0 = 0.f, v1 = 0.f, cur0 = 0.f, cur1 = 0.f;
    unsigned long long* zout = (unsigned long long*)g_zbits;
    int zslot = blockIdx.x;        // ull word per (tb): tb*16 + bx

    for (int t = 0; t < TT; t++) {
        uint4 q0 = p0, q1 = p1;
        int cnt = cnt_n;
        size_t tbn = tb + BB;
        if (t + 1 < TT) {          // prefetch next step (consumed next iter -> latency hidden)
            p0 = ((const uint4*)(g_idx + tbn * 64))[0];
            p1 = ((const uint4*)(g_idx + tbn * 64))[1];
            cnt_n = g_cnt[tbn];
        }

        unsigned w8[8] = {q0.x, q0.y, q0.z, q0.w, q1.x, q1.y, q1.z, q1.w};
        int nw = cnt >> 2;

        unsigned long long accA = 0ull, accB = 0ull;   // two packed f32x2 chains
#pragma unroll
        for (int kw = 0; kw < 8; kw++) {
            if (kw >= nw) break;
            unsigned wd = w8[kw];
            ADD2(accA, wrow[(wd & 255u) << 5]);
            ADD2(accB, wrow[((wd >> 8) & 255u) << 5]);
            ADD2(accA, wrow[((wd >> 16) & 255u) << 5]);
            ADD2(accB, wrow[(wd >> 24) << 5]);
        }
        // rare tail: more than 32 active inputs -> read index words from global
        for (int kw = 8; kw < nw; kw++) {
            unsigned wd = g_idx[tb * 64 + kw];
            ADD2(accA, wrow[(wd & 255u) << 5]);
            ADD2(accB, wrow[((wd >> 8) & 255u) << 5]);
            ADD2(accA, wrow[((wd >> 16) & 255u) << 5]);
            ADD2(accB, wrow[(wd >> 24) << 5]);
        }
        int rem = cnt & 3;
        if (rem) {
            unsigned wd;
            if (nw >= 8) {
                wd = g_idx[tb * 64 + nw];
            } else {
                wd = w8[0];
#pragma unroll
                for (int k = 1; k < 8; k++) if (nw == k) wd = w8[k];
            }
            ADD2(accA, wrow[(wd & 255u) << 5]);
            if (rem > 1) ADD2(accB, wrow[((wd >> 8) & 255u) << 5]);
            if (rem > 2) ADD2(accA, wrow[((wd >> 16) & 255u) << 5]);
        }

        float2 A, Bv;
        asm("mov.b64 {%0, %1}, %2;" : "=f"(A.x),  "=f"(A.y)  : "l"(accA));
        asm("mov.b64 {%0, %1}, %2;" : "=f"(Bv.x), "=f"(Bv.y) : "l"(accB));
        float c0 = A.x + Bv.x;
        float c1 = A.y + Bv.y;

        // CUBA LIF (exact fp32, mirrors reference)
        cur0 = cur0 * 0.875f + c0;
        v0   = v0 + 0.125f * (cur0 - v0);
        bool z0 = (v0 - 1.0f) > 0.0f;
        if (z0) v0 = 0.0f;

        cur1 = cur1 * 0.875f + c1;
        v1   = v1 + 0.125f * (cur1 - v1);
        bool z1 = (v1 - 1.0f) > 0.0f;
        if (z1) v1 = 0.0f;

        // permuted spike-bit layout: word (bx*2+0) bit p <-> h = h0 + 2p (even)
        //                            word (bx*2+1) bit p <-> h = h0 + 1 + 2p (odd)
        unsigned mE = __ballot_sync(0xffffffffu, z0);
        unsigned mO = __ballot_sync(0xffffffffu, z1);
        if (u == 0)
            zout[tb * 16 + zslot] = (unsigned long long)mE | ((unsigned long long)mO << 32);

        tb = tbn;
    }
}

// ---------------- K3: output currents from spike bitmasks + fused LI scan ----------------
// Grid 128 (one block per batch), 512 threads = 16 warps; warp handles t strided.
// smem: w_o transposed pad-33 [1024][33] + per-block c buffer [512][32].
#define COUT_SMEM (NH * 33 * 4 + TT * NOUT * 4)

__global__ __launch_bounds__(512, 1) void cout_li_kernel(const float* __restrict__ w_o,
                                                         float* __restrict__ out) {
    extern __shared__ float smem[];
    float* s_wT = smem;              // [h*33 + o]
    float* s_c  = smem + NH * 33;    // [t*32 + o]
    int tid = threadIdx.x;

    for (int k = tid; k < NOUT * NH; k += 512) {
        int o = k >> 10;
        int h = k & 1023;
        s_wT[h * 33 + o] = w_o[k];
    }
    __syncthreads();

    int b = blockIdx.x;
    int warp = tid >> 5, lane = tid & 31;

    for (int t = warp; t < TT; t += 16) {
        const unsigned* zp = g_zbits + ((size_t)t * BB + b) * 32;
        unsigned m = zp[lane];
        float c0 = 0.f, c1 = 0.f;   // two chains for ILP
#pragma unroll
        for (int wi = 0; wi < 32; wi++) {
            unsigned mw = __shfl_sync(0xffffffffu, m, wi);
            // un-permute: h = (wi>>1)*64 + (wi&1) + 2p  ->  addr = base + p*66
            int base = ((wi >> 1) * 64 + (wi & 1)) * 33 + lane;
            while (mw) {
                int p = __ffs(mw) - 1; mw &= mw - 1;
                c0 += s_wT[base + p * 66];
                if (mw) {
                    int p2 = __ffs(mw) - 1; mw &= mw - 1;
                    c1 += s_wT[base + p2 * 66];
                }
            }
        }
        s_c[t * 32 + lane] = c0 + c1;
    }
    __syncthreads();

    // fused CUBA LI readout: warp 0 scans time for this batch's 32 outputs
    if (warp == 0) {
        float v = 0.f, cur = 0.f;
        float cn = s_c[lane];
#pragma unroll 4
        for (int t = 0; t < TT; t++) {
            float c = cn;
            if (t + 1 < TT) cn = s_c[(t + 1) * 32 + lane];
            cur = cur * 0.875f + c;
            v = v + 0.125f * (cur - v);
            out[((size_t)t * BB + b) * 32 + lane] = v;
        }
    }
}

// ---------------- launch ----------------
extern "C" void kernel_launch(void* const* d_in, const int* in_sizes, int n_in,
                              void* d_out, int out_size) {
    const float* spikes = (const float*)d_in[0];   // [512,128,256]
    const float* w_h    = (const float*)d_in[1];   // [1024,256]
    const float* w_o    = (const float*)d_in[2];   // [32,1024]
    float* out = (float*)d_out;                    // [512,128,32]

    cudaFuncSetAttribute(lif_kernel,     cudaFuncAttributeMaxDynamicSharedMemorySize, LIF_SMEM);
    cudaFuncSetAttribute(cout_li_kernel, cudaFuncAttributeMaxDynamicSharedMemorySize, COUT_SMEM);

    transpose_wh_kernel<<<(NH * NIN + 1023) / 1024, 1024>>>(w_h);
    compact_kernel<<<TT * BB, 256>>>(spikes);
    lif_kernel<<<dim3(NH / 64, BB / 8), 256, LIF_SMEM>>>();
    cout_li_kernel<<<BB, 512, COUT_SMEM>>>(w_o, out);
}